// round 14
// baseline (speedup 1.0000x reference)
#include <cuda_runtime.h>
#include <cuda_bf16.h>
#include <math_constants.h>

typedef unsigned long long ull;

// ---------------- f32x2 helpers ----------------
__device__ __forceinline__ ull pk2(float lo, float hi) {
    ull r; asm("mov.b64 %0, {%1, %2};" : "=l"(r) : "f"(lo), "f"(hi)); return r;
}
__device__ __forceinline__ ull dup2(float v) {
    ull r; asm("mov.b64 %0, {%1, %1};" : "=l"(r) : "f"(v)); return r;
}
__device__ __forceinline__ void unpk2(ull v, float& lo, float& hi) {
    asm("mov.b64 {%0, %1}, %2;" : "=f"(lo), "=f"(hi) : "l"(v));
}
__device__ __forceinline__ void fma2(ull& acc, ull a, ull b) {
    asm("fma.rn.f32x2 %0, %1, %2, %0;" : "+l"(acc) : "l"(a), "l"(b));
}
__device__ __forceinline__ void lds2(ull& a, ull& b, unsigned addr) {
    asm("ld.shared.v2.u64 {%0, %1}, [%2];" : "=l"(a), "=l"(b) : "r"(addr));
}
__device__ __forceinline__ void lds128f(float& x, float& y, float& z, float& w, unsigned a) {
    asm("ld.shared.v4.f32 {%0, %1, %2, %3}, [%4];"
        : "=f"(x), "=f"(y), "=f"(z), "=f"(w) : "r"(a));
}
__device__ __forceinline__ float lds32(unsigned a) {
    float v; asm("ld.shared.f32 %0, [%1];" : "=f"(v) : "r"(a)); return v;
}
__device__ __forceinline__ ull lds64(unsigned a) {
    ull v; asm("ld.shared.b64 %0, [%1];" : "=l"(v) : "r"(a)); return v;
}
__device__ __forceinline__ void sts64(unsigned addr, ull v) {
    asm volatile("st.shared.b64 [%0], %1;" :: "r"(addr), "l"(v));
}
__device__ __forceinline__ void cpasync16(unsigned saddr, const void* g) {
    asm volatile("cp.async.ca.shared.global [%0], [%1], 16;" :: "r"(saddr), "l"(g));
}
#define CP_COMMIT()   asm volatile("cp.async.commit_group;")
#define CP_WAIT_ALL() asm volatile("cp.async.wait_group 0;")
__device__ __forceinline__ unsigned s2u(const void* p) {
    return (unsigned)__cvta_generic_to_shared(p);
}

// ---------------- scratch ----------------
__device__ __align__(16) float g_A1[2048 * 32 * 288];
__device__ __align__(16) float g_A2[1024 * 2048];      // conv2 out TRANSPOSED [feature][image]
__device__ __align__(16) float g_F1[2048 * 512];       // fc1 partial K 0..255
__device__ __align__(16) float g_F1b[2048 * 512];      // fc1 partial K 256..511
__device__ __align__(16) float g_F1c[2048 * 512];      // fc1 partial K 512..767
__device__ __align__(16) float g_F1d[2048 * 512];      // fc1 partial K 768..1023
__device__ __align__(16) float g_W2T[800 * 64];
__device__ __align__(16) float g_W1T[1024 * 512];

#define BN_INV 0.9999950000374997f

template <int NW>
__device__ __forceinline__ float blockReduce(float v) {
    __shared__ float r[NW];
    #pragma unroll
    for (int o = 16; o > 0; o >>= 1) v += __shfl_xor_sync(0xFFFFFFFFu, v, o);
    int wid = threadIdx.x >> 5, lane = threadIdx.x & 31;
    __syncthreads();
    if (lane == 0) r[wid] = v;
    __syncthreads();
    float t = 0.f;
    #pragma unroll
    for (int i = 0; i < NW; i++) t += r[i];
    return t;
}

__device__ __forceinline__ float tern_val(float v, float delta, float alpha) {
    return (v > delta) ? alpha : ((v < -delta) ? -alpha : 0.f);
}

// ---------------- k_pre ----------------
#define N_W2 (64 * 800)
#define N_W1 (512 * 1024)
__global__ void k_pre(const float* __restrict__ w2, const float* __restrict__ w1) {
    int i = blockIdx.x * 256 + threadIdx.x;
    if (i < N_W2) {
        int co = i / 800, k = i % 800;
        g_W2T[k * 64 + co] = w2[i];
    } else if (i < N_W2 + N_W1) {
        int j = i - N_W2;
        int n = j / 1024, k = j % 1024;
        g_W1T[k * 512 + n] = w1[j];
    }
}

// ================= conv1: even pairs free from lds2, odd pairs via 13 pk2/ky =================
#define SC1STR 578
__global__ void __launch_bounds__(256, 2) k_conv1(
    const float* __restrict__ x, const float* __restrict__ w,
    const float* __restrict__ bias, const float* __restrict__ bng,
    const float* __restrict__ bnb)
{
    extern __shared__ float sm[];
    float* sx  = sm;            // 784
    float* sw  = sm + 784;      // 800
    float* sc1 = sm + 1584;     // 32*578
    __shared__ float sb[32], sscale[32], sbeta[32];

    int b = blockIdx.x, tid = threadIdx.x;
    const float* xb = x + b * 784;
    for (int i = tid; i < 784; i += 256) sx[i] = xb[i];
    for (int i = tid; i < 800; i += 256) sw[i] = w[i];
    if (tid < 32) {
        sb[tid]     = bias[tid];
        sscale[tid] = bng[tid] * BN_INV;
        sbeta[tid]  = bnb[tid];
    }
    __syncthreads();

    int c = tid & 31, rg = tid >> 5;
    float wr[25];
    #pragma unroll
    for (int i = 0; i < 25; i++) wr[i] = sw[c * 25 + i];
    float bv = sb[c];

    unsigned smu = s2u(sm);
    unsigned scb = smu + (1584 + c * SC1STR) * 4;
    float asum = 0.f;

    #pragma unroll
    for (int rr = 0; rr < 3; rr++) {
        int r = rg * 3 + rr;
        ull acc[12];
        #pragma unroll
        for (int j = 0; j < 12; j++) acc[j] = dup2(bv);

        #pragma unroll
        for (int ky = 0; ky < 5; ky++) {
            unsigned xr = smu + (r + ky) * 112;   // 28 floats/row
            ull pe[14];
            #pragma unroll
            for (int q = 0; q < 7; q++) lds2(pe[2 * q], pe[2 * q + 1], xr + q * 16);
            float v[28];
            #pragma unroll
            for (int q = 0; q < 14; q++) unpk2(pe[q], v[2 * q], v[2 * q + 1]);
            ull po[13];
            #pragma unroll
            for (int q = 0; q < 13; q++) po[q] = pk2(v[2 * q + 1], v[2 * q + 2]);

            #pragma unroll
            for (int kx = 0; kx < 5; kx++) {
                ull wd = dup2(wr[ky * 5 + kx]);
                if ((kx & 1) == 0) {
                    #pragma unroll
                    for (int j = 0; j < 12; j++)
                        fma2(acc[j], pe[kx / 2 + j], wd);
                } else {
                    #pragma unroll
                    for (int j = 0; j < 12; j++)
                        fma2(acc[j], po[(kx - 1) / 2 + j], wd);
                }
            }
        }
        unsigned ro = scb + r * 24 * 4;
        #pragma unroll
        for (int j = 0; j < 12; j++) {
            sts64(ro + j * 8, acc[j]);
            float lo, hi; unpk2(acc[j], lo, hi);
            asum += fabsf(lo) + fabsf(hi);
        }
    }

    float tot = blockReduce<8>(asum);
    float delta = 0.7f * tot / 18432.0f;

    // mask sums: 36 lds64 over own 72 contiguous floats
    float ms = 0.f, mc = 0.f;
    {
        unsigned mb = scb + rg * 288;
        #pragma unroll
        for (int i = 0; i < 36; i++) {
            ull t = lds64(mb + i * 8);
            float lo, hi; unpk2(t, lo, hi);
            float a = fabsf(lo); if (a > delta) { ms += a; mc += 1.f; }
            a = fabsf(hi);       if (a > delta) { ms += a; mc += 1.f; }
        }
    }
    ms = blockReduce<8>(ms);
    mc = blockReduce<8>(mc);
    float alpha = ms / mc;

    unsigned sc1u = smu + 1584 * 4;
    for (int u = tid; u < 4608; u += 256) {
        int cc = u / 144, p = u % 144;
        int py = p / 12, px = p % 12;
        unsigned qa = sc1u + (cc * SC1STR + 48 * py + 2 * px) * 4;
        ull t0 = lds64(qa);
        ull t1 = lds64(qa + 96);
        float a0, a1, b0, b1;
        unpk2(t0, a0, a1); unpk2(t1, b0, b1);
        float sc = sscale[cc], bt = sbeta[cc];
        float m = -CUDART_INF_F;
        m = fmaxf(m, fmaf(tern_val(a0, delta, alpha), sc, bt));
        m = fmaxf(m, fmaf(tern_val(a1, delta, alpha), sc, bt));
        m = fmaxf(m, fmaf(tern_val(b0, delta, alpha), sc, bt));
        m = fmaxf(m, fmaf(tern_val(b1, delta, alpha), sc, bt));
        g_A1[b * 9216 + cc * 288 + py * 24 + px] = fmaxf(m, 0.f);
    }
}

// ================= conv2 (R13, unchanged): 2 img/block, 128 thr, warp = (img, 32-co half) =================
__global__ void __launch_bounds__(128, 2) k_conv2(
    const float* __restrict__ bias, const float* __restrict__ bng,
    const float* __restrict__ bnb)
{
    extern __shared__ float sm[];
    float* sin_ = sm;                 // 18432 floats (2 img)
    float* sov  = sm + 18432;         // 8192 floats
    __shared__ float sb2[64], sscale[64], sbeta[64];

    int b = blockIdx.x, tid = threadIdx.x;
    unsigned sin_u = s2u(sin_);
    unsigned sov_u = s2u(sov);

    const float* gin = g_A1 + b * 2 * 9216;
    #pragma unroll
    for (int i = 0; i < 36; i++) {
        int o = tid + i * 128;
        cpasync16(sin_u + o * 16, gin + o * 4);
    }
    for (int o = tid; o < 800; o += 128)
        cpasync16(sov_u + o * 16, g_W2T + o * 4);
    CP_COMMIT();

    if (tid < 64) {
        sb2[tid]    = bias[tid];
        sscale[tid] = bng[tid] * BN_INV;
        sbeta[tid]  = bnb[tid];
    }
    CP_WAIT_ALL();
    __syncthreads();

    int w = tid >> 5, lane = tid & 31;
    int iw = w >> 1, cg2 = w & 1;
    int py = lane >> 3, px = lane & 7;

    ull acc[2][16];
    #pragma unroll
    for (int j = 0; j < 16; j++) {
        ull bvj = pk2(sb2[cg2 * 32 + 2 * j], sb2[cg2 * 32 + 2 * j + 1]);
        acc[0][j] = bvj; acc[1][j] = bvj;
    }

    unsigned ax = sin_u + iw * 36864 + (py * 24 + px) * 4;
    unsigned wlane = cg2 * 128;

    for (int s = 0; s < 16; s++) {
        int cur = s & 1;
        if (s < 15) {
            const float* src = g_W2T + (s + 1) * 3200;
            unsigned dst = sov_u + (cur ^ 1) * 12800;
            for (int o = tid; o < 800; o += 128)
                cpasync16(dst + o * 16, src + o * 4);
            CP_COMMIT();
        }
        #pragma unroll
        for (int c2 = 0; c2 < 2; c2++) {
            int ci = s * 2 + c2;
            unsigned swc = sov_u + cur * 12800 + c2 * 6400 + wlane;
            unsigned a0 = ax + ci * 1152;
            #pragma unroll
            for (int t = 0; t < 25; t++) {
                const int io = ((t / 5) * 24 + (t % 5)) * 4;
                ull wv[16];
                lds2(wv[0],  wv[1],  swc + t * 256);
                lds2(wv[2],  wv[3],  swc + t * 256 + 16);
                lds2(wv[4],  wv[5],  swc + t * 256 + 32);
                lds2(wv[6],  wv[7],  swc + t * 256 + 48);
                lds2(wv[8],  wv[9],  swc + t * 256 + 64);
                lds2(wv[10], wv[11], swc + t * 256 + 80);
                lds2(wv[12], wv[13], swc + t * 256 + 96);
                lds2(wv[14], wv[15], swc + t * 256 + 112);
                float x0 = lds32(a0 + io);
                float x1 = lds32(a0 + io + 384);
                ull d;
                d = dup2(x0);
                #pragma unroll
                for (int j = 0; j < 16; j++) fma2(acc[0][j], d, wv[j]);
                d = dup2(x1);
                #pragma unroll
                for (int j = 0; j < 16; j++) fma2(acc[1][j], d, wv[j]);
            }
        }
        if (s < 15) { CP_WAIT_ALL(); __syncthreads(); }
    }

    float dlt[2], alf[2];
    #pragma unroll
    for (int img = 0; img < 2; img++) {
        float as = 0.f;
        if (iw == img) {
            #pragma unroll
            for (int pz = 0; pz < 2; pz++)
                #pragma unroll
                for (int j = 0; j < 16; j++) {
                    float lo, hi; unpk2(acc[pz][j], lo, hi);
                    as += fabsf(lo) + fabsf(hi);
                }
        }
        dlt[img] = 0.7f * blockReduce<4>(as) / 4096.0f;
    }
    #pragma unroll
    for (int img = 0; img < 2; img++) {
        float ms = 0.f, mc = 0.f;
        if (iw == img) {
            #pragma unroll
            for (int pz = 0; pz < 2; pz++)
                #pragma unroll
                for (int j = 0; j < 16; j++) {
                    float lo, hi; unpk2(acc[pz][j], lo, hi);
                    float a = fabsf(lo); if (a > dlt[img]) { ms += a; mc += 1.f; }
                    a = fabsf(hi);       if (a > dlt[img]) { ms += a; mc += 1.f; }
                }
        }
        ms = blockReduce<4>(ms);
        mc = blockReduce<4>(mc);
        alf[img] = ms / mc;
    }

    float* sout = sov;
    #pragma unroll
    for (int pz = 0; pz < 2; pz++) {
        int p = lane + pz * 32;
        #pragma unroll
        for (int j = 0; j < 16; j++) {
            float lo, hi; unpk2(acc[pz][j], lo, hi);
            sout[iw * 4096 + (cg2 * 32 + 2 * j) * 64 + p]     = lo;
            sout[iw * 4096 + (cg2 * 32 + 2 * j + 1) * 64 + p] = hi;
        }
    }
    __syncthreads();

    for (int u = tid; u < 2048; u += 128) {
        int img = u >> 10, idx = u & 1023;
        int c = idx >> 4, p = idx & 15;
        int py2 = p >> 2, px2 = p & 3;
        const float* q = sout + img * 4096 + c * 64 + (2 * py2) * 8 + 2 * px2;
        float delta = dlt[img], alpha = alf[img];
        float sc = sscale[c], bt = sbeta[c];
        float m = -CUDART_INF_F, v;
        v = q[0]; m = fmaxf(m, fmaf(tern_val(v, delta, alpha), sc, bt));
        v = q[1]; m = fmaxf(m, fmaf(tern_val(v, delta, alpha), sc, bt));
        v = q[8]; m = fmaxf(m, fmaf(tern_val(v, delta, alpha), sc, bt));
        v = q[9]; m = fmaxf(m, fmaf(tern_val(v, delta, alpha), sc, bt));
        g_A2[idx * 2048 + b * 2 + img] = fmaxf(m, 0.f);
    }
}

// ================= fc1: 64x128 tile, 8row x 4col micro, K-split z=4 =================
__global__ void __launch_bounds__(256) k_fc1()
{
    extern __shared__ float sm[];
    float* As = sm;              // [2][32][64]  16KB
    float* Bs = sm + 4096;       // [2][32][128] 32KB

    int bn = blockIdx.x * 128, bm = blockIdx.y * 64;
    int kbase = blockIdx.z * 256;
    int tid = threadIdx.x, tx = tid & 31, ty = tid >> 5;
    unsigned as_u = s2u(As), bs_u = s2u(Bs);

    ull acc[4][4];
    #pragma unroll
    for (int c = 0; c < 4; c++)
        #pragma unroll
        for (int rp = 0; rp < 4; rp++) acc[c][rp] = 0ull;

    #pragma unroll
    for (int i = 0; i < 2; i++) {
        int o = tid + i * 256;
        int kk = o >> 4, seg = o & 15;
        cpasync16(as_u + (kk * 64 + seg * 4) * 4, g_A2 + (kbase + kk) * 2048 + bm + seg * 4);
    }
    #pragma unroll
    for (int i = 0; i < 4; i++) {
        int o = tid + i * 256;
        int kk = o >> 5, seg = o & 31;
        cpasync16(bs_u + (kk * 128 + seg * 4) * 4, g_W1T + (kbase + kk) * 512 + bn + seg * 4);
    }
    CP_COMMIT();
    CP_WAIT_ALL();
    __syncthreads();

    for (int kc = 0; kc < 8; kc++) {
        int cur = kc & 1;
        if (kc < 7) {
            int k0 = kbase + (kc + 1) * 32, nb = cur ^ 1;
            #pragma unroll
            for (int i = 0; i < 2; i++) {
                int o = tid + i * 256;
                int kk = o >> 4, seg = o & 15;
                cpasync16(as_u + (nb * 2048 + kk * 64 + seg * 4) * 4,
                          g_A2 + (k0 + kk) * 2048 + bm + seg * 4);
            }
            #pragma unroll
            for (int i = 0; i < 4; i++) {
                int o = tid + i * 256;
                int kk = o >> 5, seg = o & 31;
                cpasync16(bs_u + (nb * 4096 + kk * 128 + seg * 4) * 4,
                          g_W1T + (k0 + kk) * 512 + bn + seg * 4);
            }
            CP_COMMIT();
        }
        unsigned ab = as_u + cur * 8192 + ty * 32;
        unsigned bb = bs_u + cur * 16384 + tx * 16;
        #pragma unroll
        for (int kk = 0; kk < 32; kk++) {
            ull a01, a23, a45, a67;
            lds2(a01, a23, ab + kk * 256);
            lds2(a45, a67, ab + kk * 256 + 16);
            float b0, b1, b2, b3;
            lds128f(b0, b1, b2, b3, bb + kk * 512);
            ull d;
            d = dup2(b0);
            fma2(acc[0][0], a01, d); fma2(acc[0][1], a23, d);
            fma2(acc[0][2], a45, d); fma2(acc[0][3], a67, d);
            d = dup2(b1);
            fma2(acc[1][0], a01, d); fma2(acc[1][1], a23, d);
            fma2(acc[1][2], a45, d); fma2(acc[1][3], a67, d);
            d = dup2(b2);
            fma2(acc[2][0], a01, d); fma2(acc[2][1], a23, d);
            fma2(acc[2][2], a45, d); fma2(acc[2][3], a67, d);
            d = dup2(b3);
            fma2(acc[3][0], a01, d); fma2(acc[3][1], a23, d);
            fma2(acc[3][2], a45, d); fma2(acc[3][3], a67, d);
        }
        if (kc < 7) { CP_WAIT_ALL(); __syncthreads(); }
    }

    float* dst = (blockIdx.z == 0) ? g_F1 :
                 (blockIdx.z == 1) ? g_F1b :
                 (blockIdx.z == 2) ? g_F1c : g_F1d;
    #pragma unroll
    for (int c = 0; c < 4; c++) {
        int col = bn + tx * 4 + c;
        #pragma unroll
        for (int rp = 0; rp < 4; rp++) {
            int r = bm + ty * 8 + rp * 2;
            float lo, hi; unpk2(acc[c][rp], lo, hi);
            dst[r * 512 + col]       = lo;
            dst[(r + 1) * 512 + col] = hi;
        }
    }
}

// ================= head: sum 4 partials + bias, tern+relu -> fc2 -> tern =================
__global__ void __launch_bounds__(128) k_head(
    const float* __restrict__ b1, const float* __restrict__ W2,
    const float* __restrict__ b2, float* __restrict__ out)
{
    __shared__ float sh[512];
    __shared__ float so[10];

    int b = blockIdx.x, tid = threadIdx.x;
    float4 va = ((const float4*)(g_F1  + b * 512))[tid];
    float4 vb = ((const float4*)(g_F1b + b * 512))[tid];
    float4 vc = ((const float4*)(g_F1c + b * 512))[tid];
    float4 vd = ((const float4*)(g_F1d + b * 512))[tid];
    float4 bi = ((const float4*)b1)[tid];
    float vv[4];
    vv[0] = (va.x + vb.x) + (vc.x + vd.x) + bi.x;
    vv[1] = (va.y + vb.y) + (vc.y + vd.y) + bi.y;
    vv[2] = (va.z + vb.z) + (vc.z + vd.z) + bi.z;
    vv[3] = (va.w + vb.w) + (vc.w + vd.w) + bi.w;

    float asum = fabsf(vv[0]) + fabsf(vv[1]) + fabsf(vv[2]) + fabsf(vv[3]);
    float tot = blockReduce<4>(asum);
    float delta = 0.7f * tot / 512.0f;

    float ms = 0.f, mc = 0.f;
    #pragma unroll
    for (int i = 0; i < 4; i++) {
        float a = fabsf(vv[i]);
        if (a > delta) { ms += a; mc += 1.f; }
    }
    ms = blockReduce<4>(ms);
    mc = blockReduce<4>(mc);
    float alpha = ms / mc;

    #pragma unroll
    for (int i = 0; i < 4; i++)
        sh[tid * 4 + i] = (vv[i] > delta) ? alpha : 0.f;
    __syncthreads();

    int wd = tid >> 5, ln = tid & 31;
    for (int r = wd; r < 10; r += 4) {
        float s = 0.f;
        const float* wr = W2 + r * 512;
        for (int j = ln; j < 512; j += 32) s += sh[j] * wr[j];
        #pragma unroll
        for (int o = 16; o > 0; o >>= 1) s += __shfl_xor_sync(0xFFFFFFFFu, s, o);
        if (ln == 0) so[r] = s + b2[r];
    }
    __syncthreads();

    if (tid == 0) {
        float s = 0.f;
        #pragma unroll
        for (int n = 0; n < 10; n++) s += fabsf(so[n]);
        float d2 = 0.7f * s / 10.0f;
        float ms2 = 0.f, c2 = 0.f;
        #pragma unroll
        for (int n = 0; n < 10; n++) {
            float a = fabsf(so[n]);
            if (a > d2) { ms2 += a; c2 += 1.f; }
        }
        float a2 = ms2 / c2;
        #pragma unroll
        for (int n = 0; n < 10; n++)
            out[b * 10 + n] = tern_val(so[n], d2, a2);
    }
}

// ---------------- launch ----------------
extern "C" void kernel_launch(void* const* d_in, const int* in_sizes, int n_in,
                              void* d_out, int out_size)
{
    (void)in_sizes; (void)n_in; (void)out_size;
    const float* x       = (const float*)d_in[0];
    const float* conv1_w = (const float*)d_in[1];
    const float* conv1_b = (const float*)d_in[2];
    const float* bn1_g   = (const float*)d_in[3];
    const float* bn1_b   = (const float*)d_in[4];
    const float* conv2_w = (const float*)d_in[5];
    const float* conv2_b = (const float*)d_in[6];
    const float* bn2_g   = (const float*)d_in[7];
    const float* bn2_b   = (const float*)d_in[8];
    const float* fc1_w   = (const float*)d_in[9];
    const float* fc1_b   = (const float*)d_in[10];
    const float* fc2_w   = (const float*)d_in[11];
    const float* fc2_b   = (const float*)d_in[12];
    float* out = (float*)d_out;

    const int SMEM1 = (1584 + 32 * SC1STR) * 4;          // ~80.3 KB
    const int SMEM2 = (18432 + 8192) * 4;                // 106.5 KB -> 2 CTAs/SM
    const int SMEMF = (4096 + 8192) * 4;                 // 48 KB
    cudaFuncSetAttribute(k_conv1, cudaFuncAttributeMaxDynamicSharedMemorySize, SMEM1);
    cudaFuncSetAttribute(k_conv2, cudaFuncAttributeMaxDynamicSharedMemorySize, SMEM2);
    cudaFuncSetAttribute(k_fc1,   cudaFuncAttributeMaxDynamicSharedMemorySize, SMEMF);

    k_pre<<<(N_W2 + N_W1 + 255) / 256, 256>>>(conv2_w, fc1_w);
    k_conv1<<<2048, 256, SMEM1>>>(x, conv1_w, conv1_b, bn1_g, bn1_b);
    k_conv2<<<1024, 128, SMEM2>>>(conv2_b, bn2_g, bn2_b);
    k_fc1<<<dim3(4, 32, 4), 256, SMEMF>>>();
    k_head<<<2048, 128>>>(fc1_b, fc2_w, fc2_b, out);
}

// round 15
// speedup vs baseline: 1.0488x; 1.0488x over previous
#include <cuda_runtime.h>
#include <cuda_bf16.h>
#include <math_constants.h>

typedef unsigned long long ull;

// ---------------- f32x2 helpers ----------------
__device__ __forceinline__ ull pk2(float lo, float hi) {
    ull r; asm("mov.b64 %0, {%1, %2};" : "=l"(r) : "f"(lo), "f"(hi)); return r;
}
__device__ __forceinline__ ull dup2(float v) {
    ull r; asm("mov.b64 %0, {%1, %1};" : "=l"(r) : "f"(v)); return r;
}
__device__ __forceinline__ void unpk2(ull v, float& lo, float& hi) {
    asm("mov.b64 {%0, %1}, %2;" : "=f"(lo), "=f"(hi) : "l"(v));
}
__device__ __forceinline__ void fma2(ull& acc, ull a, ull b) {
    asm("fma.rn.f32x2 %0, %1, %2, %0;" : "+l"(acc) : "l"(a), "l"(b));
}
__device__ __forceinline__ void lds2(ull& a, ull& b, unsigned addr) {
    asm("ld.shared.v2.u64 {%0, %1}, [%2];" : "=l"(a), "=l"(b) : "r"(addr));
}
__device__ __forceinline__ void lds128f(float& x, float& y, float& z, float& w, unsigned a) {
    asm("ld.shared.v4.f32 {%0, %1, %2, %3}, [%4];"
        : "=f"(x), "=f"(y), "=f"(z), "=f"(w) : "r"(a));
}
__device__ __forceinline__ float lds32(unsigned a) {
    float v; asm("ld.shared.f32 %0, [%1];" : "=f"(v) : "r"(a)); return v;
}
__device__ __forceinline__ ull lds64(unsigned a) {
    ull v; asm("ld.shared.b64 %0, [%1];" : "=l"(v) : "r"(a)); return v;
}
__device__ __forceinline__ void sts64(unsigned addr, ull v) {
    asm volatile("st.shared.b64 [%0], %1;" :: "r"(addr), "l"(v));
}
__device__ __forceinline__ void cpasync16(unsigned saddr, const void* g) {
    asm volatile("cp.async.ca.shared.global [%0], [%1], 16;" :: "r"(saddr), "l"(g));
}
#define CP_COMMIT()   asm volatile("cp.async.commit_group;")
#define CP_WAIT_ALL() asm volatile("cp.async.wait_group 0;")
__device__ __forceinline__ unsigned s2u(const void* p) {
    return (unsigned)__cvta_generic_to_shared(p);
}

// ---------------- scratch ----------------
__device__ __align__(16) float g_A1[2048 * 32 * 288];  // conv1 out [b][c][12 rows, stride 24]
__device__ __align__(16) float g_A2[1024 * 2048];      // conv2 out TRANSPOSED [feature k][image m]
__device__ __align__(16) float g_F1[2048 * 512];       // fc1 partial (K 0..511)
__device__ __align__(16) float g_F1b[2048 * 512];      // fc1 partial (K 512..1023)
__device__ __align__(16) float g_W2T[800 * 64];        // conv2 weights [k][co]
__device__ __align__(16) float g_W1T[1024 * 512];      // fc1 weights [k][n]

#define BN_INV 0.9999950000374997f

template <int NW>
__device__ __forceinline__ float blockReduce(float v) {
    __shared__ float r[NW];
    #pragma unroll
    for (int o = 16; o > 0; o >>= 1) v += __shfl_xor_sync(0xFFFFFFFFu, v, o);
    int wid = threadIdx.x >> 5, lane = threadIdx.x & 31;
    __syncthreads();
    if (lane == 0) r[wid] = v;
    __syncthreads();
    float t = 0.f;
    #pragma unroll
    for (int i = 0; i < NW; i++) t += r[i];
    return t;
}

__device__ __forceinline__ float tern_val(float v, float delta, float alpha) {
    return (v > delta) ? alpha : ((v < -delta) ? -alpha : 0.f);
}

// ---------------- k_pre: both weight transposes ----------------
#define N_W2 (64 * 800)
#define N_W1 (512 * 1024)
__global__ void k_pre(const float* __restrict__ w2, const float* __restrict__ w1) {
    int i = blockIdx.x * 256 + threadIdx.x;
    if (i < N_W2) {
        int co = i / 800, k = i % 800;
        g_W2T[k * 64 + co] = w2[i];
    } else if (i < N_W2 + N_W1) {
        int j = i - N_W2;
        int n = j / 1024, k = j % 1024;
        g_W1T[k * 512 + n] = w1[j];
    }
}

// ================= conv1: lds64 tail phases =================
#define SC1STR 578
__global__ void __launch_bounds__(256, 2) k_conv1(
    const float* __restrict__ x, const float* __restrict__ w,
    const float* __restrict__ bias, const float* __restrict__ bng,
    const float* __restrict__ bnb)
{
    extern __shared__ float sm[];
    float* sx  = sm;            // 784
    float* sw  = sm + 784;      // 800
    float* sc1 = sm + 1584;     // 32*578
    __shared__ float sb[32], sscale[32], sbeta[32];

    int b = blockIdx.x, tid = threadIdx.x;
    const float* xb = x + b * 784;
    for (int i = tid; i < 784; i += 256) sx[i] = xb[i];
    for (int i = tid; i < 800; i += 256) sw[i] = w[i];
    if (tid < 32) {
        sb[tid]     = bias[tid];
        sscale[tid] = bng[tid] * BN_INV;
        sbeta[tid]  = bnb[tid];
    }
    __syncthreads();

    int c = tid & 31, rg = tid >> 5;
    float wr[25];
    #pragma unroll
    for (int i = 0; i < 25; i++) wr[i] = sw[c * 25 + i];
    float bv = sb[c];

    unsigned scb = s2u(sm) + (1584 + c * SC1STR) * 4;
    float asum = 0.f;

    #pragma unroll
    for (int rr = 0; rr < 3; rr++) {
        int r = rg * 3 + rr;
        ull acc[12];
        #pragma unroll
        for (int j = 0; j < 12; j++) acc[j] = dup2(bv);

        #pragma unroll
        for (int ky = 0; ky < 5; ky++) {
            const float4* xr4 = (const float4*)(sx + (r + ky) * 28);
            float v[28];
            #pragma unroll
            for (int q = 0; q < 7; q++) {
                float4 t = xr4[q];
                v[q*4] = t.x; v[q*4+1] = t.y; v[q*4+2] = t.z; v[q*4+3] = t.w;
            }
            #pragma unroll
            for (int kx = 0; kx < 5; kx++) {
                ull wd = dup2(wr[ky * 5 + kx]);
                #pragma unroll
                for (int j = 0; j < 12; j++)
                    fma2(acc[j], pk2(v[kx + 2*j], v[kx + 2*j + 1]), wd);
            }
        }
        unsigned ro = scb + r * 24 * 4;
        #pragma unroll
        for (int j = 0; j < 12; j++) {
            sts64(ro + j * 8, acc[j]);
            float lo, hi; unpk2(acc[j], lo, hi);
            asum += fabsf(lo) + fabsf(hi);
        }
    }

    float tot = blockReduce<8>(asum);
    float delta = 0.7f * tot / 18432.0f;

    // mask sums: re-read own 72 contiguous floats as 36 lds64
    float ms = 0.f, mc = 0.f;
    {
        unsigned mb = scb + rg * 288;          // rows rg*3..rg*3+2 = 72 floats
        #pragma unroll
        for (int i = 0; i < 36; i++) {
            ull t = lds64(mb + i * 8);
            float lo, hi; unpk2(t, lo, hi);
            float a = fabsf(lo); if (a > delta) { ms += a; mc += 1.f; }
            a = fabsf(hi);       if (a > delta) { ms += a; mc += 1.f; }
        }
    }
    ms = blockReduce<8>(ms);
    mc = blockReduce<8>(mc);
    float alpha = ms / mc;

    // tern + BN + pool + relu -> g_A1; pairs read as lds64
    unsigned sc1u = s2u(sm) + 1584 * 4;
    for (int u = tid; u < 4608; u += 256) {
        int cc = u / 144, p = u % 144;
        int py = p / 12, px = p % 12;
        unsigned qa = sc1u + (cc * SC1STR + 48 * py + 2 * px) * 4;
        ull t0 = lds64(qa);
        ull t1 = lds64(qa + 96);               // +24 floats = next row
        float a0, a1, b0, b1;
        unpk2(t0, a0, a1); unpk2(t1, b0, b1);
        float sc = sscale[cc], bt = sbeta[cc];
        float m = -CUDART_INF_F;
        m = fmaxf(m, fmaf(tern_val(a0, delta, alpha), sc, bt));
        m = fmaxf(m, fmaf(tern_val(a1, delta, alpha), sc, bt));
        m = fmaxf(m, fmaf(tern_val(b0, delta, alpha), sc, bt));
        m = fmaxf(m, fmaf(tern_val(b1, delta, alpha), sc, bt));
        g_A1[b * 9216 + cc * 288 + py * 24 + px] = fmaxf(m, 0.f);
    }
}

// ================= conv2: 2 img/block, 128 thr, warp = (img, 32-co half) =================
__global__ void __launch_bounds__(128, 2) k_conv2(
    const float* __restrict__ bias, const float* __restrict__ bng,
    const float* __restrict__ bnb)
{
    extern __shared__ float sm[];
    float* sin_ = sm;                 // 18432 floats (2 img)
    float* sov  = sm + 18432;         // 8192 floats: wbuf dbuf 2x3200 / sout 2x4096
    __shared__ float sb2[64], sscale[64], sbeta[64];

    int b = blockIdx.x, tid = threadIdx.x;
    unsigned sin_u = s2u(sin_);
    unsigned sov_u = s2u(sov);

    const float* gin = g_A1 + b * 2 * 9216;
    #pragma unroll
    for (int i = 0; i < 36; i++) {
        int o = tid + i * 128;                 // 0..4607 float4 chunks
        cpasync16(sin_u + o * 16, gin + o * 4);
    }
    for (int o = tid; o < 800; o += 128)
        cpasync16(sov_u + o * 16, g_W2T + o * 4);
    CP_COMMIT();

    if (tid < 64) {
        sb2[tid]    = bias[tid];
        sscale[tid] = bng[tid] * BN_INV;
        sbeta[tid]  = bnb[tid];
    }
    CP_WAIT_ALL();
    __syncthreads();

    int w = tid >> 5, lane = tid & 31;
    int iw = w >> 1, cg2 = w & 1;
    int py = lane >> 3, px = lane & 7;

    ull acc[2][16];                           // [row-half][co-pair]
    #pragma unroll
    for (int j = 0; j < 16; j++) {
        ull bvj = pk2(sb2[cg2 * 32 + 2 * j], sb2[cg2 * 32 + 2 * j + 1]);
        acc[0][j] = bvj; acc[1][j] = bvj;
    }

    unsigned ax = sin_u + iw * 36864 + (py * 24 + px) * 4;
    unsigned wlane = cg2 * 128;               // 32 floats per co-half

    for (int s = 0; s < 16; s++) {
        int cur = s & 1;
        if (s < 15) {
            const float* src = g_W2T + (s + 1) * 3200;
            unsigned dst = sov_u + (cur ^ 1) * 12800;
            for (int o = tid; o < 800; o += 128)
                cpasync16(dst + o * 16, src + o * 4);
            CP_COMMIT();
        }
        #pragma unroll
        for (int c2 = 0; c2 < 2; c2++) {
            int ci = s * 2 + c2;
            unsigned swc = sov_u + cur * 12800 + c2 * 6400 + wlane;
            unsigned a0 = ax + ci * 1152;
            #pragma unroll
            for (int t = 0; t < 25; t++) {
                const int io = ((t / 5) * 24 + (t % 5)) * 4;
                ull wv[16];
                lds2(wv[0],  wv[1],  swc + t * 256);
                lds2(wv[2],  wv[3],  swc + t * 256 + 16);
                lds2(wv[4],  wv[5],  swc + t * 256 + 32);
                lds2(wv[6],  wv[7],  swc + t * 256 + 48);
                lds2(wv[8],  wv[9],  swc + t * 256 + 64);
                lds2(wv[10], wv[11], swc + t * 256 + 80);
                lds2(wv[12], wv[13], swc + t * 256 + 96);
                lds2(wv[14], wv[15], swc + t * 256 + 112);
                float x0 = lds32(a0 + io);
                float x1 = lds32(a0 + io + 384);
                ull d;
                d = dup2(x0);
                #pragma unroll
                for (int j = 0; j < 16; j++) fma2(acc[0][j], d, wv[j]);
                d = dup2(x1);
                #pragma unroll
                for (int j = 0; j < 16; j++) fma2(acc[1][j], d, wv[j]);
            }
        }
        if (s < 15) { CP_WAIT_ALL(); __syncthreads(); }
    }

    float dlt[2], alf[2];
    #pragma unroll
    for (int img = 0; img < 2; img++) {
        float as = 0.f;
        if (iw == img) {
            #pragma unroll
            for (int pz = 0; pz < 2; pz++)
                #pragma unroll
                for (int j = 0; j < 16; j++) {
                    float lo, hi; unpk2(acc[pz][j], lo, hi);
                    as += fabsf(lo) + fabsf(hi);
                }
        }
        dlt[img] = 0.7f * blockReduce<4>(as) / 4096.0f;
    }
    #pragma unroll
    for (int img = 0; img < 2; img++) {
        float ms = 0.f, mc = 0.f;
        if (iw == img) {
            #pragma unroll
            for (int pz = 0; pz < 2; pz++)
                #pragma unroll
                for (int j = 0; j < 16; j++) {
                    float lo, hi; unpk2(acc[pz][j], lo, hi);
                    float a = fabsf(lo); if (a > dlt[img]) { ms += a; mc += 1.f; }
                    a = fabsf(hi);       if (a > dlt[img]) { ms += a; mc += 1.f; }
                }
        }
        ms = blockReduce<4>(ms);
        mc = blockReduce<4>(mc);
        alf[img] = ms / mc;
    }

    float* sout = sov;
    #pragma unroll
    for (int pz = 0; pz < 2; pz++) {
        int p = lane + pz * 32;
        #pragma unroll
        for (int j = 0; j < 16; j++) {
            float lo, hi; unpk2(acc[pz][j], lo, hi);
            sout[iw * 4096 + (cg2 * 32 + 2 * j) * 64 + p]     = lo;
            sout[iw * 4096 + (cg2 * 32 + 2 * j + 1) * 64 + p] = hi;
        }
    }
    __syncthreads();

    for (int u = tid; u < 2048; u += 128) {
        int img = u >> 10, idx = u & 1023;
        int c = idx >> 4, p = idx & 15;
        int py2 = p >> 2, px2 = p & 3;
        const float* q = sout + img * 4096 + c * 64 + (2 * py2) * 8 + 2 * px2;
        float delta = dlt[img], alpha = alf[img];
        float sc = sscale[c], bt = sbeta[c];
        float m = -CUDART_INF_F, v;
        v = q[0]; m = fmaxf(m, fmaf(tern_val(v, delta, alpha), sc, bt));
        v = q[1]; m = fmaxf(m, fmaf(tern_val(v, delta, alpha), sc, bt));
        v = q[8]; m = fmaxf(m, fmaf(tern_val(v, delta, alpha), sc, bt));
        v = q[9]; m = fmaxf(m, fmaf(tern_val(v, delta, alpha), sc, bt));
        g_A2[idx * 2048 + b * 2 + img] = fmaxf(m, 0.f);
    }
}

// ================= fc1: 64x128 tile, 256 thr, 8row x 4col micro, K-split z=2 =================
__global__ void __launch_bounds__(256) k_fc1()
{
    extern __shared__ float sm[];
    float* As = sm;              // [2][32][64]  16KB
    float* Bs = sm + 4096;       // [2][32][128] 32KB

    int bn = blockIdx.x * 128, bm = blockIdx.y * 64;
    int kbase = blockIdx.z * 512;
    int tid = threadIdx.x, tx = tid & 31, ty = tid >> 5;
    unsigned as_u = s2u(As), bs_u = s2u(Bs);

    ull acc[4][4];               // [col c][row-pair rp]
    #pragma unroll
    for (int c = 0; c < 4; c++)
        #pragma unroll
        for (int rp = 0; rp < 4; rp++) acc[c][rp] = 0ull;

    #pragma unroll
    for (int i = 0; i < 2; i++) {
        int o = tid + i * 256;                 // 0..511
        int kk = o >> 4, seg = o & 15;
        cpasync16(as_u + (kk * 64 + seg * 4) * 4, g_A2 + (kbase + kk) * 2048 + bm + seg * 4);
    }
    #pragma unroll
    for (int i = 0; i < 4; i++) {
        int o = tid + i * 256;                 // 0..1023
        int kk = o >> 5, seg = o & 31;
        cpasync16(bs_u + (kk * 128 + seg * 4) * 4, g_W1T + (kbase + kk) * 512 + bn + seg * 4);
    }
    CP_COMMIT();
    CP_WAIT_ALL();
    __syncthreads();

    for (int kc = 0; kc < 16; kc++) {
        int cur = kc & 1;
        if (kc < 15) {
            int k0 = kbase + (kc + 1) * 32, nb = cur ^ 1;
            #pragma unroll
            for (int i = 0; i < 2; i++) {
                int o = tid + i * 256;
                int kk = o >> 4, seg = o & 15;
                cpasync16(as_u + (nb * 2048 + kk * 64 + seg * 4) * 4,
                          g_A2 + (k0 + kk) * 2048 + bm + seg * 4);
            }
            #pragma unroll
            for (int i = 0; i < 4; i++) {
                int o = tid + i * 256;
                int kk = o >> 5, seg = o & 31;
                cpasync16(bs_u + (nb * 4096 + kk * 128 + seg * 4) * 4,
                          g_W1T + (k0 + kk) * 512 + bn + seg * 4);
            }
            CP_COMMIT();
        }
        unsigned ab = as_u + cur * 8192 + ty * 32;     // 8 rows = 32B (warp-uniform addr)
        unsigned bb = bs_u + cur * 16384 + tx * 16;    // 4 cols = 16B
        #pragma unroll
        for (int kk = 0; kk < 32; kk++) {
            ull a01, a23, a45, a67;
            lds2(a01, a23, ab + kk * 256);
            lds2(a45, a67, ab + kk * 256 + 16);
            float b0, b1, b2, b3;
            lds128f(b0, b1, b2, b3, bb + kk * 512);
            ull d;
            d = dup2(b0);
            fma2(acc[0][0], a01, d); fma2(acc[0][1], a23, d);
            fma2(acc[0][2], a45, d); fma2(acc[0][3], a67, d);
            d = dup2(b1);
            fma2(acc[1][0], a01, d); fma2(acc[1][1], a23, d);
            fma2(acc[1][2], a45, d); fma2(acc[1][3], a67, d);
            d = dup2(b2);
            fma2(acc[2][0], a01, d); fma2(acc[2][1], a23, d);
            fma2(acc[2][2], a45, d); fma2(acc[2][3], a67, d);
            d = dup2(b3);
            fma2(acc[3][0], a01, d); fma2(acc[3][1], a23, d);
            fma2(acc[3][2], a45, d); fma2(acc[3][3], a67, d);
        }
        if (kc < 15) { CP_WAIT_ALL(); __syncthreads(); }
    }

    float* dst = blockIdx.z ? g_F1b : g_F1;
    #pragma unroll
    for (int c = 0; c < 4; c++) {
        int col = bn + tx * 4 + c;
        #pragma unroll
        for (int rp = 0; rp < 4; rp++) {
            int r = bm + ty * 8 + rp * 2;
            float lo, hi; unpk2(acc[c][rp], lo, hi);
            dst[r * 512 + col]       = lo;
            dst[(r + 1) * 512 + col] = hi;
        }
    }
}

// ================= head: sum partials + bias, tern+relu -> fc2 -> tern =================
__global__ void __launch_bounds__(128) k_head(
    const float* __restrict__ b1, const float* __restrict__ W2,
    const float* __restrict__ b2, float* __restrict__ out)
{
    __shared__ float sh[512];
    __shared__ float so[10];

    int b = blockIdx.x, tid = threadIdx.x;
    float4 va = ((const float4*)(g_F1  + b * 512))[tid];
    float4 vb = ((const float4*)(g_F1b + b * 512))[tid];
    float4 bi = ((const float4*)b1)[tid];
    float vv[4];
    vv[0] = va.x + vb.x + bi.x;
    vv[1] = va.y + vb.y + bi.y;
    vv[2] = va.z + vb.z + bi.z;
    vv[3] = va.w + vb.w + bi.w;

    float asum = fabsf(vv[0]) + fabsf(vv[1]) + fabsf(vv[2]) + fabsf(vv[3]);
    float tot = blockReduce<4>(asum);
    float delta = 0.7f * tot / 512.0f;

    float ms = 0.f, mc = 0.f;
    #pragma unroll
    for (int i = 0; i < 4; i++) {
        float a = fabsf(vv[i]);
        if (a > delta) { ms += a; mc += 1.f; }
    }
    ms = blockReduce<4>(ms);
    mc = blockReduce<4>(mc);
    float alpha = ms / mc;

    #pragma unroll
    for (int i = 0; i < 4; i++)
        sh[tid * 4 + i] = (vv[i] > delta) ? alpha : 0.f;
    __syncthreads();

    int wd = tid >> 5, ln = tid & 31;
    for (int r = wd; r < 10; r += 4) {
        float s = 0.f;
        const float* wr = W2 + r * 512;
        for (int j = ln; j < 512; j += 32) s += sh[j] * wr[j];
        #pragma unroll
        for (int o = 16; o > 0; o >>= 1) s += __shfl_xor_sync(0xFFFFFFFFu, s, o);
        if (ln == 0) so[r] = s + b2[r];
    }
    __syncthreads();

    if (tid == 0) {
        float s = 0.f;
        #pragma unroll
        for (int n = 0; n < 10; n++) s += fabsf(so[n]);
        float d2 = 0.7f * s / 10.0f;
        float ms2 = 0.f, c2 = 0.f;
        #pragma unroll
        for (int n = 0; n < 10; n++) {
            float a = fabsf(so[n]);
            if (a > d2) { ms2 += a; c2 += 1.f; }
        }
        float a2 = ms2 / c2;
        #pragma unroll
        for (int n = 0; n < 10; n++)
            out[b * 10 + n] = tern_val(so[n], d2, a2);
    }
}

// ---------------- launch ----------------
extern "C" void kernel_launch(void* const* d_in, const int* in_sizes, int n_in,
                              void* d_out, int out_size)
{
    (void)in_sizes; (void)n_in; (void)out_size;
    const float* x       = (const float*)d_in[0];
    const float* conv1_w = (const float*)d_in[1];
    const float* conv1_b = (const float*)d_in[2];
    const float* bn1_g   = (const float*)d_in[3];
    const float* bn1_b   = (const float*)d_in[4];
    const float* conv2_w = (const float*)d_in[5];
    const float* conv2_b = (const float*)d_in[6];
    const float* bn2_g   = (const float*)d_in[7];
    const float* bn2_b   = (const float*)d_in[8];
    const float* fc1_w   = (const float*)d_in[9];
    const float* fc1_b   = (const float*)d_in[10];
    const float* fc2_w   = (const float*)d_in[11];
    const float* fc2_b   = (const float*)d_in[12];
    float* out = (float*)d_out;

    const int SMEM1 = (1584 + 32 * SC1STR) * 4;          // ~80.3 KB
    const int SMEM2 = (18432 + 8192) * 4;                // 106.5 KB -> 2 CTAs/SM
    const int SMEMF = (4096 + 8192) * 4;                 // 48 KB
    cudaFuncSetAttribute(k_conv1, cudaFuncAttributeMaxDynamicSharedMemorySize, SMEM1);
    cudaFuncSetAttribute(k_conv2, cudaFuncAttributeMaxDynamicSharedMemorySize, SMEM2);
    cudaFuncSetAttribute(k_fc1,   cudaFuncAttributeMaxDynamicSharedMemorySize, SMEMF);

    k_pre<<<(N_W2 + N_W1 + 255) / 256, 256>>>(conv2_w, fc1_w);
    k_conv1<<<2048, 256, SMEM1>>>(x, conv1_w, conv1_b, bn1_g, bn1_b);
    k_conv2<<<1024, 128, SMEM2>>>(conv2_b, bn2_g, bn2_b);
    k_fc1<<<dim3(4, 32, 2), 256, SMEMF>>>();
    k_head<<<2048, 128>>>(fc1_b, fc2_w, fc2_b, out);
}

// round 16
// speedup vs baseline: 1.0523x; 1.0034x over previous
#include <cuda_runtime.h>
#include <cuda_bf16.h>
#include <math_constants.h>

typedef unsigned long long ull;

// ---------------- f32x2 helpers ----------------
__device__ __forceinline__ ull pk2(float lo, float hi) {
    ull r; asm("mov.b64 %0, {%1, %2};" : "=l"(r) : "f"(lo), "f"(hi)); return r;
}
__device__ __forceinline__ ull dup2(float v) {
    ull r; asm("mov.b64 %0, {%1, %1};" : "=l"(r) : "f"(v)); return r;
}
__device__ __forceinline__ void unpk2(ull v, float& lo, float& hi) {
    asm("mov.b64 {%0, %1}, %2;" : "=f"(lo), "=f"(hi) : "l"(v));
}
__device__ __forceinline__ void fma2(ull& acc, ull a, ull b) {
    asm("fma.rn.f32x2 %0, %1, %2, %0;" : "+l"(acc) : "l"(a), "l"(b));
}
__device__ __forceinline__ void lds2(ull& a, ull& b, unsigned addr) {
    asm("ld.shared.v2.u64 {%0, %1}, [%2];" : "=l"(a), "=l"(b) : "r"(addr));
}
__device__ __forceinline__ void lds128f(float& x, float& y, float& z, float& w, unsigned a) {
    asm("ld.shared.v4.f32 {%0, %1, %2, %3}, [%4];"
        : "=f"(x), "=f"(y), "=f"(z), "=f"(w) : "r"(a));
}
__device__ __forceinline__ float lds32(unsigned a) {
    float v; asm("ld.shared.f32 %0, [%1];" : "=f"(v) : "r"(a)); return v;
}
__device__ __forceinline__ ull lds64(unsigned a) {
    ull v; asm("ld.shared.b64 %0, [%1];" : "=l"(v) : "r"(a)); return v;
}
__device__ __forceinline__ void sts64(unsigned addr, ull v) {
    asm volatile("st.shared.b64 [%0], %1;" :: "r"(addr), "l"(v));
}
__device__ __forceinline__ void cpasync16(unsigned saddr, const void* g) {
    asm volatile("cp.async.ca.shared.global [%0], [%1], 16;" :: "r"(saddr), "l"(g));
}
#define CP_COMMIT()   asm volatile("cp.async.commit_group;")
#define CP_WAIT_ALL() asm volatile("cp.async.wait_group 0;")
__device__ __forceinline__ unsigned s2u(const void* p) {
    return (unsigned)__cvta_generic_to_shared(p);
}

// ---------------- scratch ----------------
__device__ __align__(16) float g_A1[2048 * 32 * 288];  // conv1 out [b][c][12 rows, stride 24]
__device__ __align__(16) float g_A2[1024 * 2048];      // conv2 out TRANSPOSED [feature k][image m]
__device__ __align__(16) float g_F1[2048 * 512];       // fc1 partial (K 0..511)
__device__ __align__(16) float g_F1b[2048 * 512];      // fc1 partial (K 512..1023)
__device__ __align__(16) float g_W2T[800 * 64];        // conv2 weights [k][co]
__device__ __align__(16) float g_W1T[1024 * 512];      // fc1 weights [k][n]

#define BN_INV 0.9999950000374997f

template <int NW>
__device__ __forceinline__ float blockReduce(float v) {
    __shared__ float r[NW];
    #pragma unroll
    for (int o = 16; o > 0; o >>= 1) v += __shfl_xor_sync(0xFFFFFFFFu, v, o);
    int wid = threadIdx.x >> 5, lane = threadIdx.x & 31;
    __syncthreads();
    if (lane == 0) r[wid] = v;
    __syncthreads();
    float t = 0.f;
    #pragma unroll
    for (int i = 0; i < NW; i++) t += r[i];
    return t;
}

__device__ __forceinline__ float tern_val(float v, float delta, float alpha) {
    return (v > delta) ? alpha : ((v < -delta) ? -alpha : 0.f);
}

// ================= conv1 (+ folded weight transposes) =================
#define SC1STR 578
#define N_W2 (64 * 800)
#define N_W1 (512 * 1024)
#define N_WT (N_W2 + N_W1)      // 575488 elements; 2048 blocks -> 281/block
__global__ void __launch_bounds__(256, 2) k_conv1(
    const float* __restrict__ x, const float* __restrict__ w,
    const float* __restrict__ bias, const float* __restrict__ bng,
    const float* __restrict__ bnb,
    const float* __restrict__ w2full, const float* __restrict__ w1full)
{
    extern __shared__ float sm[];
    float* sx  = sm;            // 784
    float* sw  = sm + 784;      // 800
    float* sc1 = sm + 1584;     // 32*578
    __shared__ float sb[32], sscale[32], sbeta[32];

    int b = blockIdx.x, tid = threadIdx.x;
    const float* xb = x + b * 784;
    for (int i = tid; i < 784; i += 256) sx[i] = xb[i];
    for (int i = tid; i < 800; i += 256) sw[i] = w[i];
    if (tid < 32) {
        sb[tid]     = bias[tid];
        sscale[tid] = bng[tid] * BN_INV;
        sbeta[tid]  = bnb[tid];
    }
    __syncthreads();

    int c = tid & 31, rg = tid >> 5;
    float wr[25];
    #pragma unroll
    for (int i = 0; i < 25; i++) wr[i] = sw[c * 25 + i];
    float bv = sb[c];

    unsigned scb = s2u(sm) + (1584 + c * SC1STR) * 4;
    float asum = 0.f;

    #pragma unroll
    for (int rr = 0; rr < 3; rr++) {
        int r = rg * 3 + rr;
        ull acc[12];
        #pragma unroll
        for (int j = 0; j < 12; j++) acc[j] = dup2(bv);

        #pragma unroll
        for (int ky = 0; ky < 5; ky++) {
            const float4* xr4 = (const float4*)(sx + (r + ky) * 28);
            float v[28];
            #pragma unroll
            for (int q = 0; q < 7; q++) {
                float4 t = xr4[q];
                v[q*4] = t.x; v[q*4+1] = t.y; v[q*4+2] = t.z; v[q*4+3] = t.w;
            }
            #pragma unroll
            for (int kx = 0; kx < 5; kx++) {
                ull wd = dup2(wr[ky * 5 + kx]);
                #pragma unroll
                for (int j = 0; j < 12; j++)
                    fma2(acc[j], pk2(v[kx + 2*j], v[kx + 2*j + 1]), wd);
            }
        }
        unsigned ro = scb + r * 24 * 4;
        #pragma unroll
        for (int j = 0; j < 12; j++) {
            sts64(ro + j * 8, acc[j]);
            float lo, hi; unpk2(acc[j], lo, hi);
            asum += fabsf(lo) + fabsf(hi);
        }
    }

    float tot = blockReduce<8>(asum);
    float delta = 0.7f * tot / 18432.0f;

    // mask sums: re-read own 72 contiguous floats as 36 lds64
    float ms = 0.f, mc = 0.f;
    {
        unsigned mb = scb + rg * 288;
        #pragma unroll
        for (int i = 0; i < 36; i++) {
            ull t = lds64(mb + i * 8);
            float lo, hi; unpk2(t, lo, hi);
            float a = fabsf(lo); if (a > delta) { ms += a; mc += 1.f; }
            a = fabsf(hi);       if (a > delta) { ms += a; mc += 1.f; }
        }
    }
    ms = blockReduce<8>(ms);
    mc = blockReduce<8>(mc);
    float alpha = ms / mc;

    // tern + BN + pool + relu -> g_A1; pairs read as lds64
    unsigned sc1u = s2u(sm) + 1584 * 4;
    for (int u = tid; u < 4608; u += 256) {
        int cc = u / 144, p = u % 144;
        int py = p / 12, px = p % 12;
        unsigned qa = sc1u + (cc * SC1STR + 48 * py + 2 * px) * 4;
        ull t0 = lds64(qa);
        ull t1 = lds64(qa + 96);
        float a0, a1, b0, b1;
        unpk2(t0, a0, a1); unpk2(t1, b0, b1);
        float sc = sscale[cc], bt = sbeta[cc];
        float m = -CUDART_INF_F;
        m = fmaxf(m, fmaf(tern_val(a0, delta, alpha), sc, bt));
        m = fmaxf(m, fmaf(tern_val(a1, delta, alpha), sc, bt));
        m = fmaxf(m, fmaf(tern_val(b0, delta, alpha), sc, bt));
        m = fmaxf(m, fmaf(tern_val(b1, delta, alpha), sc, bt));
        g_A1[b * 9216 + cc * 288 + py * 24 + px] = fmaxf(m, 0.f);
    }

    // folded weight transposes (consumed only by later kernels)
    for (int i = b * 256 + tid; i < N_WT; i += 2048 * 256) {
        if (i < N_W2) {
            int co = i / 800, k = i % 800;
            g_W2T[k * 64 + co] = w2full[i];
        } else {
            int j = i - N_W2;
            int n = j / 1024, k = j % 1024;
            g_W1T[k * 512 + n] = w1full[j];
        }
    }
}

// ================= conv2: 2 img/block, 128 thr, warp = (img, 32-co half) =================
__global__ void __launch_bounds__(128, 2) k_conv2(
    const float* __restrict__ bias, const float* __restrict__ bng,
    const float* __restrict__ bnb)
{
    extern __shared__ float sm[];
    float* sin_ = sm;                 // 18432 floats (2 img)
    float* sov  = sm + 18432;         // 8192 floats: wbuf dbuf 2x3200 / sout 2x4096
    __shared__ float sb2[64], sscale[64], sbeta[64];

    int b = blockIdx.x, tid = threadIdx.x;
    unsigned sin_u = s2u(sin_);
    unsigned sov_u = s2u(sov);

    const float* gin = g_A1 + b * 2 * 9216;
    #pragma unroll
    for (int i = 0; i < 36; i++) {
        int o = tid + i * 128;
        cpasync16(sin_u + o * 16, gin + o * 4);
    }
    for (int o = tid; o < 800; o += 128)
        cpasync16(sov_u + o * 16, g_W2T + o * 4);
    CP_COMMIT();

    if (tid < 64) {
        sb2[tid]    = bias[tid];
        sscale[tid] = bng[tid] * BN_INV;
        sbeta[tid]  = bnb[tid];
    }
    CP_WAIT_ALL();
    __syncthreads();

    int w = tid >> 5, lane = tid & 31;
    int iw = w >> 1, cg2 = w & 1;
    int py = lane >> 3, px = lane & 7;

    ull acc[2][16];
    #pragma unroll
    for (int j = 0; j < 16; j++) {
        ull bvj = pk2(sb2[cg2 * 32 + 2 * j], sb2[cg2 * 32 + 2 * j + 1]);
        acc[0][j] = bvj; acc[1][j] = bvj;
    }

    unsigned ax = sin_u + iw * 36864 + (py * 24 + px) * 4;
    unsigned wlane = cg2 * 128;

    for (int s = 0; s < 16; s++) {
        int cur = s & 1;
        if (s < 15) {
            const float* src = g_W2T + (s + 1) * 3200;
            unsigned dst = sov_u + (cur ^ 1) * 12800;
            for (int o = tid; o < 800; o += 128)
                cpasync16(dst + o * 16, src + o * 4);
            CP_COMMIT();
        }
        #pragma unroll
        for (int c2 = 0; c2 < 2; c2++) {
            int ci = s * 2 + c2;
            unsigned swc = sov_u + cur * 12800 + c2 * 6400 + wlane;
            unsigned a0 = ax + ci * 1152;
            #pragma unroll
            for (int t = 0; t < 25; t++) {
                const int io = ((t / 5) * 24 + (t % 5)) * 4;
                ull wv[16];
                lds2(wv[0],  wv[1],  swc + t * 256);
                lds2(wv[2],  wv[3],  swc + t * 256 + 16);
                lds2(wv[4],  wv[5],  swc + t * 256 + 32);
                lds2(wv[6],  wv[7],  swc + t * 256 + 48);
                lds2(wv[8],  wv[9],  swc + t * 256 + 64);
                lds2(wv[10], wv[11], swc + t * 256 + 80);
                lds2(wv[12], wv[13], swc + t * 256 + 96);
                lds2(wv[14], wv[15], swc + t * 256 + 112);
                float x0 = lds32(a0 + io);
                float x1 = lds32(a0 + io + 384);
                ull d;
                d = dup2(x0);
                #pragma unroll
                for (int j = 0; j < 16; j++) fma2(acc[0][j], d, wv[j]);
                d = dup2(x1);
                #pragma unroll
                for (int j = 0; j < 16; j++) fma2(acc[1][j], d, wv[j]);
            }
        }
        if (s < 15) { CP_WAIT_ALL(); __syncthreads(); }
    }

    float dlt[2], alf[2];
    #pragma unroll
    for (int img = 0; img < 2; img++) {
        float as = 0.f;
        if (iw == img) {
            #pragma unroll
            for (int pz = 0; pz < 2; pz++)
                #pragma unroll
                for (int j = 0; j < 16; j++) {
                    float lo, hi; unpk2(acc[pz][j], lo, hi);
                    as += fabsf(lo) + fabsf(hi);
                }
        }
        dlt[img] = 0.7f * blockReduce<4>(as) / 4096.0f;
    }
    #pragma unroll
    for (int img = 0; img < 2; img++) {
        float ms = 0.f, mc = 0.f;
        if (iw == img) {
            #pragma unroll
            for (int pz = 0; pz < 2; pz++)
                #pragma unroll
                for (int j = 0; j < 16; j++) {
                    float lo, hi; unpk2(acc[pz][j], lo, hi);
                    float a = fabsf(lo); if (a > dlt[img]) { ms += a; mc += 1.f; }
                    a = fabsf(hi);       if (a > dlt[img]) { ms += a; mc += 1.f; }
                }
        }
        ms = blockReduce<4>(ms);
        mc = blockReduce<4>(mc);
        alf[img] = ms / mc;
    }

    float* sout = sov;
    #pragma unroll
    for (int pz = 0; pz < 2; pz++) {
        int p = lane + pz * 32;
        #pragma unroll
        for (int j = 0; j < 16; j++) {
            float lo, hi; unpk2(acc[pz][j], lo, hi);
            sout[iw * 4096 + (cg2 * 32 + 2 * j) * 64 + p]     = lo;
            sout[iw * 4096 + (cg2 * 32 + 2 * j + 1) * 64 + p] = hi;
        }
    }
    __syncthreads();

    for (int u = tid; u < 2048; u += 128) {
        int img = u >> 10, idx = u & 1023;
        int c = idx >> 4, p = idx & 15;
        int py2 = p >> 2, px2 = p & 3;
        const float* q = sout + img * 4096 + c * 64 + (2 * py2) * 8 + 2 * px2;
        float delta = dlt[img], alpha = alf[img];
        float sc = sscale[c], bt = sbeta[c];
        float m = -CUDART_INF_F, v;
        v = q[0]; m = fmaxf(m, fmaf(tern_val(v, delta, alpha), sc, bt));
        v = q[1]; m = fmaxf(m, fmaf(tern_val(v, delta, alpha), sc, bt));
        v = q[8]; m = fmaxf(m, fmaf(tern_val(v, delta, alpha), sc, bt));
        v = q[9]; m = fmaxf(m, fmaf(tern_val(v, delta, alpha), sc, bt));
        g_A2[idx * 2048 + b * 2 + img] = fmaxf(m, 0.f);
    }
}

// ================= fc1: 64x128 tile, 256 thr, 8row x 4col micro, K-split z=2 =================
__global__ void __launch_bounds__(256) k_fc1()
{
    extern __shared__ float sm[];
    float* As = sm;              // [2][32][64]  16KB
    float* Bs = sm + 4096;       // [2][32][128] 32KB

    int bn = blockIdx.x * 128, bm = blockIdx.y * 64;
    int kbase = blockIdx.z * 512;
    int tid = threadIdx.x, tx = tid & 31, ty = tid >> 5;
    unsigned as_u = s2u(As), bs_u = s2u(Bs);

    ull acc[4][4];
    #pragma unroll
    for (int c = 0; c < 4; c++)
        #pragma unroll
        for (int rp = 0; rp < 4; rp++) acc[c][rp] = 0ull;

    #pragma unroll
    for (int i = 0; i < 2; i++) {
        int o = tid + i * 256;
        int kk = o >> 4, seg = o & 15;
        cpasync16(as_u + (kk * 64 + seg * 4) * 4, g_A2 + (kbase + kk) * 2048 + bm + seg * 4);
    }
    #pragma unroll
    for (int i = 0; i < 4; i++) {
        int o = tid + i * 256;
        int kk = o >> 5, seg = o & 31;
        cpasync16(bs_u + (kk * 128 + seg * 4) * 4, g_W1T + (kbase + kk) * 512 + bn + seg * 4);
    }
    CP_COMMIT();
    CP_WAIT_ALL();
    __syncthreads();

    for (int kc = 0; kc < 16; kc++) {
        int cur = kc & 1;
        if (kc < 15) {
            int k0 = kbase + (kc + 1) * 32, nb = cur ^ 1;
            #pragma unroll
            for (int i = 0; i < 2; i++) {
                int o = tid + i * 256;
                int kk = o >> 4, seg = o & 15;
                cpasync16(as_u + (nb * 2048 + kk * 64 + seg * 4) * 4,
                          g_A2 + (k0 + kk) * 2048 + bm + seg * 4);
            }
            #pragma unroll
            for (int i = 0; i < 4; i++) {
                int o = tid + i * 256;
                int kk = o >> 5, seg = o & 31;
                cpasync16(bs_u + (nb * 4096 + kk * 128 + seg * 4) * 4,
                          g_W1T + (k0 + kk) * 512 + bn + seg * 4);
            }
            CP_COMMIT();
        }
        unsigned ab = as_u + cur * 8192 + ty * 32;
        unsigned bb = bs_u + cur * 16384 + tx * 16;
        #pragma unroll
        for (int kk = 0; kk < 32; kk++) {
            ull a01, a23, a45, a67;
            lds2(a01, a23, ab + kk * 256);
            lds2(a45, a67, ab + kk * 256 + 16);
            float b0, b1, b2, b3;
            lds128f(b0, b1, b2, b3, bb + kk * 512);
            ull d;
            d = dup2(b0);
            fma2(acc[0][0], a01, d); fma2(acc[0][1], a23, d);
            fma2(acc[0][2], a45, d); fma2(acc[0][3], a67, d);
            d = dup2(b1);
            fma2(acc[1][0], a01, d); fma2(acc[1][1], a23, d);
            fma2(acc[1][2], a45, d); fma2(acc[1][3], a67, d);
            d = dup2(b2);
            fma2(acc[2][0], a01, d); fma2(acc[2][1], a23, d);
            fma2(acc[2][2], a45, d); fma2(acc[2][3], a67, d);
            d = dup2(b3);
            fma2(acc[3][0], a01, d); fma2(acc[3][1], a23, d);
            fma2(acc[3][2], a45, d); fma2(acc[3][3], a67, d);
        }
        if (kc < 15) { CP_WAIT_ALL(); __syncthreads(); }
    }

    float* dst = blockIdx.z ? g_F1b : g_F1;
    #pragma unroll
    for (int c = 0; c < 4; c++) {
        int col = bn + tx * 4 + c;
        #pragma unroll
        for (int rp = 0; rp < 4; rp++) {
            int r = bm + ty * 8 + rp * 2;
            float lo, hi; unpk2(acc[c][rp], lo, hi);
            dst[r * 512 + col]       = lo;
            dst[(r + 1) * 512 + col] = hi;
        }
    }
}

// ================= head: sum partials + bias, tern+relu -> fc2 (float4) -> tern =================
__global__ void __launch_bounds__(128) k_head(
    const float* __restrict__ b1, const float* __restrict__ W2,
    const float* __restrict__ b2, float* __restrict__ out)
{
    __shared__ __align__(16) float sh[512];
    __shared__ float so[10];

    int b = blockIdx.x, tid = threadIdx.x;
    float4 va = ((const float4*)(g_F1  + b * 512))[tid];
    float4 vb = ((const float4*)(g_F1b + b * 512))[tid];
    float4 bi = ((const float4*)b1)[tid];
    float vv[4];
    vv[0] = va.x + vb.x + bi.x;
    vv[1] = va.y + vb.y + bi.y;
    vv[2] = va.z + vb.z + bi.z;
    vv[3] = va.w + vb.w + bi.w;

    float asum = fabsf(vv[0]) + fabsf(vv[1]) + fabsf(vv[2]) + fabsf(vv[3]);
    float tot = blockReduce<4>(asum);
    float delta = 0.7f * tot / 512.0f;

    float ms = 0.f, mc = 0.f;
    #pragma unroll
    for (int i = 0; i < 4; i++) {
        float a = fabsf(vv[i]);
        if (a > delta) { ms += a; mc += 1.f; }
    }
    ms = blockReduce<4>(ms);
    mc = blockReduce<4>(mc);
    float alpha = ms / mc;

    #pragma unroll
    for (int i = 0; i < 4; i++)
        sh[tid * 4 + i] = (vv[i] > delta) ? alpha : 0.f;
    __syncthreads();

    // fc2: float4 dot products; warp wd handles rows wd, wd+4, wd+8
    int wd = tid >> 5, ln = tid & 31;
    const float4* sh4 = (const float4*)sh;
    for (int r = wd; r < 10; r += 4) {
        const float4* wr4 = (const float4*)(W2 + r * 512);
        float s = 0.f;
        #pragma unroll
        for (int j = 0; j < 4; j++) {
            float4 hv = sh4[ln + j * 32];
            float4 wv = wr4[ln + j * 32];
            s += hv.x * wv.x + hv.y * wv.y + hv.z * wv.z + hv.w * wv.w;
        }
        #pragma unroll
        for (int o = 16; o > 0; o >>= 1) s += __shfl_xor_sync(0xFFFFFFFFu, s, o);
        if (ln == 0) so[r] = s + b2[r];
    }
    __syncthreads();

    if (tid == 0) {
        float s = 0.f;
        #pragma unroll
        for (int n = 0; n < 10; n++) s += fabsf(so[n]);
        float d2 = 0.7f * s / 10.0f;
        float ms2 = 0.f, c2 = 0.f;
        #pragma unroll
        for (int n = 0; n < 10; n++) {
            float a = fabsf(so[n]);
            if (a > d2) { ms2 += a; c2 += 1.f; }
        }
        float a2 = ms2 / c2;
        #pragma unroll
        for (int n = 0; n < 10; n++)
            out[b * 10 + n] = tern_val(so[n], d2, a2);
    }
}

// ---------------- launch ----------------
extern "C" void kernel_launch(void* const* d_in, const int* in_sizes, int n_in,
                              void* d_out, int out_size)
{
    (void)in_sizes; (void)n_in; (void)out_size;
    const float* x       = (const float*)d_in[0];
    const float* conv1_w = (const float*)d_in[1];
    const float* conv1_b = (const float*)d_in[2];
    const float* bn1_g   = (const float*)d_in[3];
    const float* bn1_b   = (const float*)d_in[4];
    const float* conv2_w = (const float*)d_in[5];
    const float* conv2_b = (const float*)d_in[6];
    const float* bn2_g   = (const float*)d_in[7];
    const float* bn2_b   = (const float*)d_in[8];
    const float* fc1_w   = (const float*)d_in[9];
    const float* fc1_b   = (const float*)d_in[10];
    const float* fc2_w   = (const float*)d_in[11];
    const float* fc2_b   = (const float*)d_in[12];
    float* out = (float*)d_out;

    const int SMEM1 = (1584 + 32 * SC1STR) * 4;          // ~80.3 KB
    const int SMEM2 = (18432 + 8192) * 4;                // 106.5 KB -> 2 CTAs/SM
    const int SMEMF = (4096 + 8192) * 4;                 // 48 KB
    cudaFuncSetAttribute(k_conv1, cudaFuncAttributeMaxDynamicSharedMemorySize, SMEM1);
    cudaFuncSetAttribute(k_conv2, cudaFuncAttributeMaxDynamicSharedMemorySize, SMEM2);
    cudaFuncSetAttribute(k_fc1,   cudaFuncAttributeMaxDynamicSharedMemorySize, SMEMF);

    k_conv1<<<2048, 256, SMEM1>>>(x, conv1_w, conv1_b, bn1_g, bn1_b, conv2_w, fc1_w);
    k_conv2<<<1024, 128, SMEM2>>>(conv2_b, bn2_g, bn2_b);
    k_fc1<<<dim3(4, 32, 2), 256, SMEMF>>>();
    k_head<<<2048, 128>>>(fc1_b, fc2_w, fc2_b, out);
}